// round 16
// baseline (speedup 1.0000x reference)
#include <cuda_runtime.h>
#include <cuda_fp16.h>
#include <cstdint>

#define BB 2
#define CC 128
#define NN 4096
#define LOG2E 1.4426950408889634f

// Device scratch
__device__ __half g_qh[BB * NN * CC];      // [b][n][c]  fp16, pre-scaled by log2e
__device__ __half g_kh[BB * NN * CC];      // [b][n][c]  fp16
__device__ __half g_vh[BB * CC * NN];      // [b][c][n]  fp16
__device__ __half g_ph[4 * BB * CC * NN];  // [quad][b][c][n] partial O (fp16)
__device__ float g_lsum[4 * BB * NN];      // [quad][b][n] partial row sums

// ============================ helpers ============================
__device__ __forceinline__ uint32_t smem_u32(const void* p) {
    uint32_t a;
    asm("{ .reg .u64 t; cvta.to.shared.u64 t, %1; cvt.u32.u64 %0, t; }"
        : "=r"(a) : "l"(p));
    return a;
}
__device__ __forceinline__ uint32_t ex2_h2(uint32_t x) {
    uint32_t r;
    asm("ex2.approx.f16x2 %0, %1;" : "=r"(r) : "r"(x));
    return r;
}
__device__ __forceinline__ uint32_t pack_h2(float lo, float hi) {
    __half2 h = __floats2half2_rn(lo, hi);
    return *reinterpret_cast<uint32_t*>(&h);
}

#define MMA_F16(d, a, b0, b1) \
    asm volatile("mma.sync.aligned.m16n8k16.row.col.f32.f16.f16.f32 " \
        "{%0,%1,%2,%3}, {%4,%5,%6,%7}, {%8,%9}, {%0,%1,%2,%3};" \
        : "+f"((d)[0]), "+f"((d)[1]), "+f"((d)[2]), "+f"((d)[3]) \
        : "r"((a)[0]), "r"((a)[1]), "r"((a)[2]), "r"((a)[3]), "r"(b0), "r"(b1))

#define LDSM_X4(r0, r1, r2, r3, addr) \
    asm volatile("ldmatrix.sync.aligned.m8n8.x4.shared.b16 {%0,%1,%2,%3}, [%4];" \
        : "=r"(r0), "=r"(r1), "=r"(r2), "=r"(r3) : "r"(addr))

#define CPA(dst, src) \
    asm volatile("cp.async.cg.shared.global [%0], [%1], 16;" :: "r"(dst), "l"(src))
#define CPA_COMMIT asm volatile("cp.async.commit_group;" ::: "memory")
#define CPA_WAIT0  asm volatile("cp.async.wait_group 0;" ::: "memory")
#define CPA_WAIT1  asm volatile("cp.async.wait_group 1;" ::: "memory")

// ============================ QKV: merged 1-wave, 3xFP16 split GEMM (R13 proven) ============================
#define WS 132
#define OFF_W1  16896
#define OFF_XF  33792
#define OFF_XHI 43008
#define OFF_XLO 47360
#define SMEM_QKV (51712 * 4)
#define INV64 0.015625f

__global__ __launch_bounds__(256, 1)
void qkv5(const float* __restrict__ x,
          const float* __restrict__ Wq, const float* __restrict__ bq,
          const float* __restrict__ Wk, const float* __restrict__ bk,
          const float* __restrict__ Wv, const float* __restrict__ bv) {
    extern __shared__ float sm[];
    uint32_t sbase = smem_u32(sm);

    int n0 = blockIdx.x * 64;
    int b = blockIdx.y;
    const float* xb = x + (size_t)b * CC * NN;
    const float* Bm[3] = {bq, bk, bv};

    int tid = threadIdx.x;
    int w = tid >> 5, lane = tid & 31;
    int g = lane >> 2, t = lane & 3;
    int crow = w * 16 + g;

    #pragma unroll
    for (int it = 0; it < 16; it++) {
        int i = tid + it * 256;
        int r = i >> 5, c4 = (i & 31) << 2;
        CPA(sbase + (uint32_t)(r * WS + c4) * 4, Wq + (size_t)r * CC + c4);
    }
    CPA_COMMIT;
    #pragma unroll
    for (int it = 0; it < 8; it++) {
        int i = tid + it * 256;
        int r = i >> 4, n4 = (i & 15) << 2;
        CPA(sbase + (uint32_t)(OFF_XF + r * 72 + n4) * 4, xb + (size_t)r * NN + n0 + n4);
    }
    CPA_COMMIT;
    #pragma unroll
    for (int it = 0; it < 16; it++) {
        int i = tid + it * 256;
        int r = i >> 5, c4 = (i & 31) << 2;
        CPA(sbase + (uint32_t)(OFF_W1 + r * WS + c4) * 4, Wk + (size_t)r * CC + c4);
    }
    CPA_COMMIT;

    CPA_WAIT1;
    __syncthreads();

    {
        int n = tid >> 2;
        int kbase = (tid & 3) * 32;
        uint32_t* XhiT = (uint32_t*)sm + OFF_XHI;
        uint32_t* XloT = (uint32_t*)sm + OFF_XLO;
        #pragma unroll
        for (int j = 0; j < 16; j++) {
            int k = kbase + 2 * j;
            float f0 = sm[OFF_XF + k * 72 + n];
            float f1 = sm[OFF_XF + (k + 1) * 72 + n];
            __half h0 = __float2half_rn(f0), h1 = __float2half_rn(f1);
            XhiT[n * 68 + (kbase >> 1) + j] = pack_h2(__half2float(h0), __half2float(h1));
            XloT[n * 68 + (kbase >> 1) + j] = pack_h2(f0 - __half2float(h0), f1 - __half2float(h1));
        }
    }
    __syncthreads();

    const uint32_t* Xhi = (const uint32_t*)sm + OFF_XHI;
    const uint32_t* Xlo = (const uint32_t*)sm + OFF_XLO;

    #pragma unroll 1
    for (int m = 0; m < 3; m++) {
        const float* Wb = sm + ((m & 1) ? OFF_W1 : 0);

        uint32_t wa_hi[8][4], wa_lo[8][4];
        #pragma unroll
        for (int ko = 0; ko < 8; ko++) {
            #pragma unroll
            for (int q = 0; q < 4; q++) {
                int row = crow + ((q & 1) ? 8 : 0);
                int kk = ko * 16 + 2 * t + ((q >> 1) ? 8 : 0);
                float2 p = *(const float2*)&Wb[row * WS + kk];
                p.x *= 64.0f; p.y *= 64.0f;
                __half h0 = __float2half_rn(p.x), h1 = __float2half_rn(p.y);
                wa_hi[ko][q] = pack_h2(__half2float(h0), __half2float(h1));
                wa_lo[ko][q] = pack_h2(p.x - __half2float(h0), p.y - __half2float(h1));
            }
        }
        __syncthreads();

        if (m == 0) {
            #pragma unroll
            for (int it = 0; it < 16; it++) {
                int i = tid + it * 256;
                int r = i >> 5, c4 = (i & 31) << 2;
                CPA(sbase + (uint32_t)(r * WS + c4) * 4, Wv + (size_t)r * CC + c4);
            }
            CPA_COMMIT;
        }

        float acc[8][4] = {};
        #pragma unroll
        for (int ko = 0; ko < 8; ko++) {
            #pragma unroll
            for (int nt = 0; nt < 8; nt++) {
                int i0 = (nt * 8 + g) * 68 + ko * 8 + t;
                uint32_t bh0 = Xhi[i0], bh1 = Xhi[i0 + 4];
                uint32_t bl0 = Xlo[i0], bl1 = Xlo[i0 + 4];
                MMA_F16(acc[nt], wa_lo[ko], bh0, bh1);
                MMA_F16(acc[nt], wa_hi[ko], bl0, bl1);
                MMA_F16(acc[nt], wa_hi[ko], bh0, bh1);
            }
        }
        __syncthreads();

        const float* bias = Bm[m];
        float b0v = bias[crow], b1v = bias[crow + 8];
        float qs = (m == 0) ? LOG2E : 1.0f;
        __half* st_h = (__half*)(sm + OFF_XF);

        if (m != 2) {
            #pragma unroll
            for (int nt = 0; nt < 8; nt++) {
                int n = nt * 8 + 2 * t;
                st_h[n * 136 + crow]           = __float2half_rn((acc[nt][0] * INV64 + b0v) * qs);
                st_h[(n + 1) * 136 + crow]     = __float2half_rn((acc[nt][1] * INV64 + b0v) * qs);
                st_h[n * 136 + crow + 8]       = __float2half_rn((acc[nt][2] * INV64 + b1v) * qs);
                st_h[(n + 1) * 136 + crow + 8] = __float2half_rn((acc[nt][3] * INV64 + b1v) * qs);
            }
            __syncthreads();
            __half* out = ((m == 0) ? g_qh : g_kh) + ((size_t)b * NN + n0) * CC;
            #pragma unroll
            for (int it = 0; it < 4; it++) {
                int i = tid + it * 256;
                int r = i >> 4, c8 = (i & 15) << 3;
                *(uint4*)(out + (size_t)r * CC + c8) = *(uint4*)&st_h[r * 136 + c8];
            }
        } else {
            #pragma unroll
            for (int nt = 0; nt < 8; nt++) {
                int n = nt * 8 + 2 * t;
                *(__half2*)&st_h[crow * 72 + n] =
                    __floats2half2_rn(acc[nt][0] * INV64 + b0v, acc[nt][1] * INV64 + b0v);
                *(__half2*)&st_h[(crow + 8) * 72 + n] =
                    __floats2half2_rn(acc[nt][2] * INV64 + b1v, acc[nt][3] * INV64 + b1v);
            }
            __syncthreads();
            __half* out = g_vh + (size_t)b * CC * NN + n0;
            #pragma unroll
            for (int it = 0; it < 4; it++) {
                int i = tid + it * 256;
                int r = i >> 3, n8 = (i & 7) << 3;
                *(uint4*)(out + (size_t)r * NN + n8) = *(uint4*)&st_h[r * 72 + n8];
            }
        }

        if (m == 0) CPA_WAIT1;
        if (m == 1) CPA_WAIT0;
        __syncthreads();
    }
}

// ============================ flash v11: m32 warp tile (B-frag reuse x2) ============================
// CTA: 256 q rows (8 warps x m32), 1024 keys in 8 blocks of 128. 256 threads.
// grid (16 qtiles, 4 kquads, 2 b) = 128 CTAs.
// SMEM halves (stride 136): Q[256][136] | K 2x[128][136] | V 2x[128][136] = 204 KB
#define FS 136
#define OFFQ 0
#define OFFK 34816
#define KB 17408
#define OFFV 69632
#define VB 17408
#define SMEM_FLASH11 (104448 * 2)
#define ONES2 0x3C003C00u

__global__ __launch_bounds__(256, 1)
void flash11() {
    extern __shared__ __half smh[];
    uint32_t sbase = smem_u32(smh);

    int tid = threadIdx.x;
    int w = tid >> 5, lane = tid & 31;
    int g = lane >> 2, t = lane & 3;

    int lrow = (lane & 7) + ((lane >> 4) & 1) * 8;
    int lkof = ((lane >> 3) & 1) * 8;
    uint32_t laneoff = (uint32_t)(lrow * FS + lkof) * 2;

    int qtile = blockIdx.x, quad = blockIdx.y, b = blockIdx.z;
    const __half* qg = g_qh + ((size_t)b * NN + (size_t)qtile * 256) * CC;
    const __half* kg = g_kh + ((size_t)b * NN + (size_t)quad * 1024) * CC;
    const __half* vg = g_vh + (size_t)b * CC * NN + (size_t)quad * 1024;

    // ---- prologue: Q (256 rows), K0, V0 ----
    #pragma unroll
    for (int it = 0; it < 16; it++) {
        int i = tid + it * 256;
        int r = i >> 4, c16 = i & 15;
        CPA(sbase + (uint32_t)(r * FS * 2 + c16 * 16), qg + (size_t)r * CC + c16 * 8);
    }
    #pragma unroll
    for (int it = 0; it < 8; it++) {
        int i = tid + it * 256;
        int r = i >> 4, c16 = i & 15;
        CPA(sbase + (uint32_t)(OFFK * 2 + r * FS * 2 + c16 * 16), kg + (size_t)r * CC + c16 * 8);
    }
    #pragma unroll
    for (int it = 0; it < 8; it++) {
        int i = tid + it * 256;
        int c = i >> 4, k16 = i & 15;
        CPA(sbase + (uint32_t)(OFFV * 2 + c * FS * 2 + k16 * 16), vg + (size_t)c * NN + k16 * 8);
    }
    CPA_COMMIT;
    CPA_WAIT0;
    __syncthreads();

    // Q ldmatrix bases for the warp's two m16 tiles
    uint32_t qbase0 = sbase + (uint32_t)((w * 32 + lrow) * FS + lkof) * 2;
    uint32_t qbase1 = qbase0 + (uint32_t)(16 * FS) * 2;

    float o[2][16][4] = {};
    float rsacc[2][4] = {};

    for (int kb = 0; kb < 8; kb++) {
        int buf = kb & 1;
        if (kb < 7) {
            int m0g = (kb + 1) * 128;
            int nb = buf ^ 1;
            #pragma unroll
            for (int it = 0; it < 8; it++) {
                int i = tid + it * 256;
                int r = i >> 4, c16 = i & 15;
                CPA(sbase + (uint32_t)((OFFK + nb * KB) * 2 + r * FS * 2 + c16 * 16),
                    kg + (size_t)(m0g + r) * CC + c16 * 8);
            }
            #pragma unroll
            for (int it = 0; it < 8; it++) {
                int i = tid + it * 256;
                int c = i >> 4, k16 = i & 15;
                CPA(sbase + (uint32_t)((OFFV + nb * VB) * 2 + c * FS * 2 + k16 * 16),
                    vg + (size_t)c * NN + m0g + k16 * 8);
            }
            CPA_COMMIT;
        }

        uint32_t kaddr = sbase + (uint32_t)(OFFK + buf * KB) * 2 + laneoff;
        uint32_t vaddr = sbase + (uint32_t)(OFFV + buf * VB) * 2 + laneoff;

        #pragma unroll
        for (int nh = 0; nh < 2; nh++) {
            // ---- S: m32 x n64, k=128; Q frags reloaded (LDSM), K frags reused by both m-tiles ----
            float sacc[2][8][4] = {};
            #pragma unroll
            for (int ko = 0; ko < 8; ko++) {
                uint32_t q0[4], q1[4];
                LDSM_X4(q0[0], q0[2], q0[1], q0[3], qbase0 + (uint32_t)(ko * 16) * 2);
                LDSM_X4(q1[0], q1[2], q1[1], q1[3], qbase1 + (uint32_t)(ko * 16) * 2);
                #pragma unroll
                for (int np = 0; np < 4; np++) {
                    uint32_t a = kaddr + (uint32_t)(((nh * 4 + np) * 16) * FS + ko * 16) * 2;
                    uint32_t r0, r1, r2, r3;
                    LDSM_X4(r0, r1, r2, r3, a);
                    MMA_F16(sacc[0][np * 2 + 0], q0, r0, r1);
                    MMA_F16(sacc[0][np * 2 + 1], q0, r2, r3);
                    MMA_F16(sacc[1][np * 2 + 0], q1, r0, r1);
                    MMA_F16(sacc[1][np * 2 + 1], q1, r2, r3);
                }
            }

            // ---- P = 2^S (f16x2 MUFU), pack to A-frags ----
            uint32_t pa[2][4][4];
            #pragma unroll
            for (int mi = 0; mi < 2; mi++) {
                #pragma unroll
                for (int nt = 0; nt < 8; nt++) {
                    pa[mi][nt >> 1][(nt & 1) * 2 + 0] =
                        ex2_h2(pack_h2(sacc[mi][nt][0], sacc[mi][nt][1]));
                    pa[mi][nt >> 1][(nt & 1) * 2 + 1] =
                        ex2_h2(pack_h2(sacc[mi][nt][2], sacc[mi][nt][3]));
                }
            }

            // ---- rowsums via ones-MMA ----
            #pragma unroll
            for (int kf = 0; kf < 4; kf++) {
                MMA_F16(rsacc[0], pa[0][kf], ONES2, ONES2);
                MMA_F16(rsacc[1], pa[1][kf], ONES2, ONES2);
            }

            // ---- O += P V for this n-half's keys (V frags reused by both m-tiles) ----
            #pragma unroll
            for (int kf = 0; kf < 4; kf++) {
                #pragma unroll
                for (int cp = 0; cp < 8; cp++) {
                    uint32_t a = vaddr + (uint32_t)((cp * 16) * FS + nh * 64 + kf * 16) * 2;
                    uint32_t r0, r1, r2, r3;
                    LDSM_X4(r0, r1, r2, r3, a);
                    MMA_F16(o[0][cp * 2 + 0], pa[0][kf], r0, r1);
                    MMA_F16(o[0][cp * 2 + 1], pa[0][kf], r2, r3);
                    MMA_F16(o[1][cp * 2 + 0], pa[1][kf], r0, r1);
                    MMA_F16(o[1][cp * 2 + 1], pa[1][kf], r2, r3);
                }
            }
        }

        CPA_WAIT0;
        __syncthreads();
    }

    // ---- rowsums (fully reduced by MMA; lanes within row-group identical) ----
    if (t == 0) {
        float* gl = g_lsum + ((size_t)quad * BB + b) * NN + (size_t)qtile * 256;
        int qr = w * 32 + g;
        gl[qr]      = rsacc[0][0];
        gl[qr + 8]  = rsacc[0][2];
        gl[qr + 16] = rsacc[1][0];
        gl[qr + 24] = rsacc[1][2];
    }

    // ---- stage O as fp16 [c][q] stride 272 (reuses Q region: 128*272 = 34816 halves) ----
    __half* st = smh;
    #pragma unroll
    for (int mi = 0; mi < 2; mi++) {
        int q0 = w * 32 + mi * 16 + g;
        #pragma unroll
        for (int cn = 0; cn < 16; cn++) {
            int c0 = cn * 8 + 2 * t;
            st[c0 * 272 + q0]           = __float2half_rn(o[mi][cn][0]);
            st[(c0 + 1) * 272 + q0]     = __float2half_rn(o[mi][cn][1]);
            st[c0 * 272 + q0 + 8]       = __float2half_rn(o[mi][cn][2]);
            st[(c0 + 1) * 272 + q0 + 8] = __float2half_rn(o[mi][cn][3]);
        }
    }
    __syncthreads();
    __half* gp = g_ph + ((size_t)quad * BB + b) * CC * NN + (size_t)qtile * 256;
    #pragma unroll
    for (int it = 0; it < 16; it++) {
        int i = tid + it * 256;
        int c = i >> 5, q8 = (i & 31) << 3;
        *(uint4*)(gp + (size_t)c * NN + q8) = *(uint4*)&st[c * 272 + q8];
    }
}

// ============================ combine quads (fp16 partials) ============================
__global__ __launch_bounds__(256)
void combine_kernel(float* __restrict__ out) {
    int idx = blockIdx.x * 256 + threadIdx.x;
    size_t e = (size_t)idx * 8;
    int n = (int)(e & (NN - 1));
    int b = (int)((e >> 19) & 1);             // CC*NN = 2^19

    float num[8] = {};
    float den[8] = {};
    #pragma unroll
    for (int p = 0; p < 4; p++) {
        uint4 u = *(const uint4*)(g_ph + (size_t)p * BB * CC * NN + e);
        float2 f0 = __half22float2(*(__half2*)&u.x);
        float2 f1 = __half22float2(*(__half2*)&u.y);
        float2 f2 = __half22float2(*(__half2*)&u.z);
        float2 f3 = __half22float2(*(__half2*)&u.w);
        num[0] += f0.x; num[1] += f0.y; num[2] += f1.x; num[3] += f1.y;
        num[4] += f2.x; num[5] += f2.y; num[6] += f3.x; num[7] += f3.y;
        const float* lp = g_lsum + ((size_t)p * BB + b) * NN + n;
        float4 la = *(const float4*)lp;
        float4 lb = *(const float4*)(lp + 4);
        den[0] += la.x; den[1] += la.y; den[2] += la.z; den[3] += la.w;
        den[4] += lb.x; den[5] += lb.y; den[6] += lb.z; den[7] += lb.w;
    }
    float4 r0, r1;
    r0.x = num[0] / den[0]; r0.y = num[1] / den[1];
    r0.z = num[2] / den[2]; r0.w = num[3] / den[3];
    r1.x = num[4] / den[4]; r1.y = num[5] / den[5];
    r1.z = num[6] / den[6]; r1.w = num[7] / den[7];
    *(float4*)(out + e) = r0;
    *(float4*)(out + e + 4) = r1;
}

// ============================ launch ============================
extern "C" void kernel_launch(void* const* d_in, const int* in_sizes, int n_in,
                              void* d_out, int out_size) {
    const float* x  = (const float*)d_in[0];
    const float* Wq = (const float*)d_in[1];
    const float* bq = (const float*)d_in[2];
    const float* Wk = (const float*)d_in[3];
    const float* bk = (const float*)d_in[4];
    const float* Wv = (const float*)d_in[5];
    const float* bv = (const float*)d_in[6];
    float* out = (float*)d_out;

    cudaFuncSetAttribute(qkv5, cudaFuncAttributeMaxDynamicSharedMemorySize, SMEM_QKV);
    dim3 gq(NN / 64, BB);
    qkv5<<<gq, 256, SMEM_QKV>>>(x, Wq, bq, Wk, bk, Wv, bv);

    cudaFuncSetAttribute(flash11, cudaFuncAttributeMaxDynamicSharedMemorySize, SMEM_FLASH11);
    dim3 gf(NN / 256, 4, BB);
    flash11<<<gf, 256, SMEM_FLASH11>>>();

    combine_kernel<<<(BB * CC * NN / 8) / 256, 256>>>(out);
}

// round 17
// speedup vs baseline: 1.0113x; 1.0113x over previous
#include <cuda_runtime.h>
#include <cuda_fp16.h>
#include <cstdint>

#define BB 2
#define CC 128
#define NN 4096
#define LOG2E 1.4426950408889634f

// Device scratch
__device__ __half g_qh[BB * NN * CC];      // [b][n][c]  fp16, pre-scaled by log2e
__device__ __half g_kh[BB * NN * CC];      // [b][n][c]  fp16
__device__ __half g_vh[BB * CC * NN];      // [b][c][n]  fp16
__device__ __half g_ph[4 * BB * CC * NN];  // [quad][b][c][n] partial O (fp16)
__device__ float g_lsum[4 * BB * NN];      // [quad][b][n] partial row sums

// ============================ helpers ============================
__device__ __forceinline__ uint32_t smem_u32(const void* p) {
    uint32_t a;
    asm("{ .reg .u64 t; cvta.to.shared.u64 t, %1; cvt.u32.u64 %0, t; }"
        : "=r"(a) : "l"(p));
    return a;
}
__device__ __forceinline__ uint32_t ex2_h2(uint32_t x) {
    uint32_t r;
    asm("ex2.approx.f16x2 %0, %1;" : "=r"(r) : "r"(x));
    return r;
}
__device__ __forceinline__ uint32_t pack_h2(float lo, float hi) {
    __half2 h = __floats2half2_rn(lo, hi);
    return *reinterpret_cast<uint32_t*>(&h);
}

#define MMA_F16(d, a, b0, b1) \
    asm volatile("mma.sync.aligned.m16n8k16.row.col.f32.f16.f16.f32 " \
        "{%0,%1,%2,%3}, {%4,%5,%6,%7}, {%8,%9}, {%0,%1,%2,%3};" \
        : "+f"((d)[0]), "+f"((d)[1]), "+f"((d)[2]), "+f"((d)[3]) \
        : "r"((a)[0]), "r"((a)[1]), "r"((a)[2]), "r"((a)[3]), "r"(b0), "r"(b1))

#define LDSM_X4(r0, r1, r2, r3, addr) \
    asm volatile("ldmatrix.sync.aligned.m8n8.x4.shared.b16 {%0,%1,%2,%3}, [%4];" \
        : "=r"(r0), "=r"(r1), "=r"(r2), "=r"(r3) : "r"(addr))

#define CPA(dst, src) \
    asm volatile("cp.async.cg.shared.global [%0], [%1], 16;" :: "r"(dst), "l"(src))
#define CPA_COMMIT asm volatile("cp.async.commit_group;" ::: "memory")
#define CPA_WAIT0  asm volatile("cp.async.wait_group 0;" ::: "memory")
#define CPA_WAIT1  asm volatile("cp.async.wait_group 1;" ::: "memory")

// ============================ QKV: merged 1-wave, 3xFP16 split GEMM (R13 proven) ============================
#define WS 132
#define OFF_W1  16896
#define OFF_XF  33792
#define OFF_XHI 43008
#define OFF_XLO 47360
#define SMEM_QKV (51712 * 4)
#define INV64 0.015625f

__global__ __launch_bounds__(256, 1)
void qkv5(const float* __restrict__ x,
          const float* __restrict__ Wq, const float* __restrict__ bq,
          const float* __restrict__ Wk, const float* __restrict__ bk,
          const float* __restrict__ Wv, const float* __restrict__ bv) {
    extern __shared__ float sm[];
    uint32_t sbase = smem_u32(sm);

    int n0 = blockIdx.x * 64;
    int b = blockIdx.y;
    const float* xb = x + (size_t)b * CC * NN;
    const float* Bm[3] = {bq, bk, bv};

    int tid = threadIdx.x;
    int w = tid >> 5, lane = tid & 31;
    int g = lane >> 2, t = lane & 3;
    int crow = w * 16 + g;

    #pragma unroll
    for (int it = 0; it < 16; it++) {
        int i = tid + it * 256;
        int r = i >> 5, c4 = (i & 31) << 2;
        CPA(sbase + (uint32_t)(r * WS + c4) * 4, Wq + (size_t)r * CC + c4);
    }
    CPA_COMMIT;
    #pragma unroll
    for (int it = 0; it < 8; it++) {
        int i = tid + it * 256;
        int r = i >> 4, n4 = (i & 15) << 2;
        CPA(sbase + (uint32_t)(OFF_XF + r * 72 + n4) * 4, xb + (size_t)r * NN + n0 + n4);
    }
    CPA_COMMIT;
    #pragma unroll
    for (int it = 0; it < 16; it++) {
        int i = tid + it * 256;
        int r = i >> 5, c4 = (i & 31) << 2;
        CPA(sbase + (uint32_t)(OFF_W1 + r * WS + c4) * 4, Wk + (size_t)r * CC + c4);
    }
    CPA_COMMIT;

    CPA_WAIT1;
    __syncthreads();

    {
        int n = tid >> 2;
        int kbase = (tid & 3) * 32;
        uint32_t* XhiT = (uint32_t*)sm + OFF_XHI;
        uint32_t* XloT = (uint32_t*)sm + OFF_XLO;
        #pragma unroll
        for (int j = 0; j < 16; j++) {
            int k = kbase + 2 * j;
            float f0 = sm[OFF_XF + k * 72 + n];
            float f1 = sm[OFF_XF + (k + 1) * 72 + n];
            __half h0 = __float2half_rn(f0), h1 = __float2half_rn(f1);
            XhiT[n * 68 + (kbase >> 1) + j] = pack_h2(__half2float(h0), __half2float(h1));
            XloT[n * 68 + (kbase >> 1) + j] = pack_h2(f0 - __half2float(h0), f1 - __half2float(h1));
        }
    }
    __syncthreads();

    const uint32_t* Xhi = (const uint32_t*)sm + OFF_XHI;
    const uint32_t* Xlo = (const uint32_t*)sm + OFF_XLO;

    #pragma unroll 1
    for (int m = 0; m < 3; m++) {
        const float* Wb = sm + ((m & 1) ? OFF_W1 : 0);

        uint32_t wa_hi[8][4], wa_lo[8][4];
        #pragma unroll
        for (int ko = 0; ko < 8; ko++) {
            #pragma unroll
            for (int q = 0; q < 4; q++) {
                int row = crow + ((q & 1) ? 8 : 0);
                int kk = ko * 16 + 2 * t + ((q >> 1) ? 8 : 0);
                float2 p = *(const float2*)&Wb[row * WS + kk];
                p.x *= 64.0f; p.y *= 64.0f;
                __half h0 = __float2half_rn(p.x), h1 = __float2half_rn(p.y);
                wa_hi[ko][q] = pack_h2(__half2float(h0), __half2float(h1));
                wa_lo[ko][q] = pack_h2(p.x - __half2float(h0), p.y - __half2float(h1));
            }
        }
        __syncthreads();

        if (m == 0) {
            #pragma unroll
            for (int it = 0; it < 16; it++) {
                int i = tid + it * 256;
                int r = i >> 5, c4 = (i & 31) << 2;
                CPA(sbase + (uint32_t)(r * WS + c4) * 4, Wv + (size_t)r * CC + c4);
            }
            CPA_COMMIT;
        }

        float acc[8][4] = {};
        #pragma unroll
        for (int ko = 0; ko < 8; ko++) {
            #pragma unroll
            for (int nt = 0; nt < 8; nt++) {
                int i0 = (nt * 8 + g) * 68 + ko * 8 + t;
                uint32_t bh0 = Xhi[i0], bh1 = Xhi[i0 + 4];
                uint32_t bl0 = Xlo[i0], bl1 = Xlo[i0 + 4];
                MMA_F16(acc[nt], wa_lo[ko], bh0, bh1);
                MMA_F16(acc[nt], wa_hi[ko], bl0, bl1);
                MMA_F16(acc[nt], wa_hi[ko], bh0, bh1);
            }
        }
        __syncthreads();

        const float* bias = Bm[m];
        float b0v = bias[crow], b1v = bias[crow + 8];
        float qs = (m == 0) ? LOG2E : 1.0f;
        __half* st_h = (__half*)(sm + OFF_XF);

        if (m != 2) {
            #pragma unroll
            for (int nt = 0; nt < 8; nt++) {
                int n = nt * 8 + 2 * t;
                st_h[n * 136 + crow]           = __float2half_rn((acc[nt][0] * INV64 + b0v) * qs);
                st_h[(n + 1) * 136 + crow]     = __float2half_rn((acc[nt][1] * INV64 + b0v) * qs);
                st_h[n * 136 + crow + 8]       = __float2half_rn((acc[nt][2] * INV64 + b1v) * qs);
                st_h[(n + 1) * 136 + crow + 8] = __float2half_rn((acc[nt][3] * INV64 + b1v) * qs);
            }
            __syncthreads();
            __half* out = ((m == 0) ? g_qh : g_kh) + ((size_t)b * NN + n0) * CC;
            #pragma unroll
            for (int it = 0; it < 4; it++) {
                int i = tid + it * 256;
                int r = i >> 4, c8 = (i & 15) << 3;
                *(uint4*)(out + (size_t)r * CC + c8) = *(uint4*)&st_h[r * 136 + c8];
            }
        } else {
            #pragma unroll
            for (int nt = 0; nt < 8; nt++) {
                int n = nt * 8 + 2 * t;
                *(__half2*)&st_h[crow * 72 + n] =
                    __floats2half2_rn(acc[nt][0] * INV64 + b0v, acc[nt][1] * INV64 + b0v);
                *(__half2*)&st_h[(crow + 8) * 72 + n] =
                    __floats2half2_rn(acc[nt][2] * INV64 + b1v, acc[nt][3] * INV64 + b1v);
            }
            __syncthreads();
            __half* out = g_vh + (size_t)b * CC * NN + n0;
            #pragma unroll
            for (int it = 0; it < 4; it++) {
                int i = tid + it * 256;
                int r = i >> 3, n8 = (i & 7) << 3;
                *(uint4*)(out + (size_t)r * NN + n8) = *(uint4*)&st_h[r * 72 + n8];
            }
        }

        if (m == 0) CPA_WAIT1;
        if (m == 1) CPA_WAIT0;
        __syncthreads();
    }
}

// ============================ flash v11: m32 warp tile (B-frag reuse x2) ============================
// CTA: 256 q rows (8 warps x m32), 1024 keys in 8 blocks of 128. 256 threads.
// grid (16 qtiles, 4 kquads, 2 b) = 128 CTAs.
// SMEM halves (stride 136): Q[256][136] | K 2x[128][136] | V 2x[128][136] = 204 KB
#define FS 136
#define OFFQ 0
#define OFFK 34816
#define KB 17408
#define OFFV 69632
#define VB 17408
#define SMEM_FLASH11 (104448 * 2)
#define ONES2 0x3C003C00u

__global__ __launch_bounds__(256, 1)
void flash11() {
    extern __shared__ __half smh[];
    uint32_t sbase = smem_u32(smh);

    int tid = threadIdx.x;
    int w = tid >> 5, lane = tid & 31;
    int g = lane >> 2, t = lane & 3;

    int lrow = (lane & 7) + ((lane >> 4) & 1) * 8;
    int lkof = ((lane >> 3) & 1) * 8;
    uint32_t laneoff = (uint32_t)(lrow * FS + lkof) * 2;

    int qtile = blockIdx.x, quad = blockIdx.y, b = blockIdx.z;
    const __half* qg = g_qh + ((size_t)b * NN + (size_t)qtile * 256) * CC;
    const __half* kg = g_kh + ((size_t)b * NN + (size_t)quad * 1024) * CC;
    const __half* vg = g_vh + (size_t)b * CC * NN + (size_t)quad * 1024;

    // ---- prologue: Q (256 rows), K0, V0 ----
    #pragma unroll
    for (int it = 0; it < 16; it++) {
        int i = tid + it * 256;
        int r = i >> 4, c16 = i & 15;
        CPA(sbase + (uint32_t)(r * FS * 2 + c16 * 16), qg + (size_t)r * CC + c16 * 8);
    }
    #pragma unroll
    for (int it = 0; it < 8; it++) {
        int i = tid + it * 256;
        int r = i >> 4, c16 = i & 15;
        CPA(sbase + (uint32_t)(OFFK * 2 + r * FS * 2 + c16 * 16), kg + (size_t)r * CC + c16 * 8);
    }
    #pragma unroll
    for (int it = 0; it < 8; it++) {
        int i = tid + it * 256;
        int c = i >> 4, k16 = i & 15;
        CPA(sbase + (uint32_t)(OFFV * 2 + c * FS * 2 + k16 * 16), vg + (size_t)c * NN + k16 * 8);
    }
    CPA_COMMIT;
    CPA_WAIT0;
    __syncthreads();

    // Q ldmatrix bases for the warp's two m16 tiles
    uint32_t qbase0 = sbase + (uint32_t)((w * 32 + lrow) * FS + lkof) * 2;
    uint32_t qbase1 = qbase0 + (uint32_t)(16 * FS) * 2;

    float o[2][16][4] = {};
    float rsacc[2][4] = {};

    for (int kb = 0; kb < 8; kb++) {
        int buf = kb & 1;
        if (kb < 7) {
            int m0g = (kb + 1) * 128;
            int nb = buf ^ 1;
            #pragma unroll
            for (int it = 0; it < 8; it++) {
                int i = tid + it * 256;
                int r = i >> 4, c16 = i & 15;
                CPA(sbase + (uint32_t)((OFFK + nb * KB) * 2 + r * FS * 2 + c16 * 16),
                    kg + (size_t)(m0g + r) * CC + c16 * 8);
            }
            #pragma unroll
            for (int it = 0; it < 8; it++) {
                int i = tid + it * 256;
                int c = i >> 4, k16 = i & 15;
                CPA(sbase + (uint32_t)((OFFV + nb * VB) * 2 + c * FS * 2 + k16 * 16),
                    vg + (size_t)c * NN + m0g + k16 * 8);
            }
            CPA_COMMIT;
        }

        uint32_t kaddr = sbase + (uint32_t)(OFFK + buf * KB) * 2 + laneoff;
        uint32_t vaddr = sbase + (uint32_t)(OFFV + buf * VB) * 2 + laneoff;

        #pragma unroll
        for (int nh = 0; nh < 2; nh++) {
            // ---- S: m32 x n64, k=128; Q frags reloaded (LDSM), K frags reused by both m-tiles ----
            float sacc[2][8][4] = {};
            #pragma unroll
            for (int ko = 0; ko < 8; ko++) {
                uint32_t q0[4], q1[4];
                LDSM_X4(q0[0], q0[2], q0[1], q0[3], qbase0 + (uint32_t)(ko * 16) * 2);
                LDSM_X4(q1[0], q1[2], q1[1], q1[3], qbase1 + (uint32_t)(ko * 16) * 2);
                #pragma unroll
                for (int np = 0; np < 4; np++) {
                    uint32_t a = kaddr + (uint32_t)(((nh * 4 + np) * 16) * FS + ko * 16) * 2;
                    uint32_t r0, r1, r2, r3;
                    LDSM_X4(r0, r1, r2, r3, a);
                    MMA_F16(sacc[0][np * 2 + 0], q0, r0, r1);
                    MMA_F16(sacc[0][np * 2 + 1], q0, r2, r3);
                    MMA_F16(sacc[1][np * 2 + 0], q1, r0, r1);
                    MMA_F16(sacc[1][np * 2 + 1], q1, r2, r3);
                }
            }

            // ---- P = 2^S (f16x2 MUFU), pack to A-frags ----
            uint32_t pa[2][4][4];
            #pragma unroll
            for (int mi = 0; mi < 2; mi++) {
                #pragma unroll
                for (int nt = 0; nt < 8; nt++) {
                    pa[mi][nt >> 1][(nt & 1) * 2 + 0] =
                        ex2_h2(pack_h2(sacc[mi][nt][0], sacc[mi][nt][1]));
                    pa[mi][nt >> 1][(nt & 1) * 2 + 1] =
                        ex2_h2(pack_h2(sacc[mi][nt][2], sacc[mi][nt][3]));
                }
            }

            // ---- rowsums via ones-MMA ----
            #pragma unroll
            for (int kf = 0; kf < 4; kf++) {
                MMA_F16(rsacc[0], pa[0][kf], ONES2, ONES2);
                MMA_F16(rsacc[1], pa[1][kf], ONES2, ONES2);
            }

            // ---- O += P V for this n-half's keys (V frags reused by both m-tiles) ----
            #pragma unroll
            for (int kf = 0; kf < 4; kf++) {
                #pragma unroll
                for (int cp = 0; cp < 8; cp++) {
                    uint32_t a = vaddr + (uint32_t)((cp * 16) * FS + nh * 64 + kf * 16) * 2;
                    uint32_t r0, r1, r2, r3;
                    LDSM_X4(r0, r1, r2, r3, a);
                    MMA_F16(o[0][cp * 2 + 0], pa[0][kf], r0, r1);
                    MMA_F16(o[0][cp * 2 + 1], pa[0][kf], r2, r3);
                    MMA_F16(o[1][cp * 2 + 0], pa[1][kf], r0, r1);
                    MMA_F16(o[1][cp * 2 + 1], pa[1][kf], r2, r3);
                }
            }
        }

        CPA_WAIT0;
        __syncthreads();
    }

    // ---- rowsums (fully reduced by MMA; lanes within row-group identical) ----
    if (t == 0) {
        float* gl = g_lsum + ((size_t)quad * BB + b) * NN + (size_t)qtile * 256;
        int qr = w * 32 + g;
        gl[qr]      = rsacc[0][0];
        gl[qr + 8]  = rsacc[0][2];
        gl[qr + 16] = rsacc[1][0];
        gl[qr + 24] = rsacc[1][2];
    }

    // ---- stage O as fp16 [c][q] stride 272 (reuses Q region: 128*272 = 34816 halves) ----
    __half* st = smh;
    #pragma unroll
    for (int mi = 0; mi < 2; mi++) {
        int q0 = w * 32 + mi * 16 + g;
        #pragma unroll
        for (int cn = 0; cn < 16; cn++) {
            int c0 = cn * 8 + 2 * t;
            st[c0 * 272 + q0]           = __float2half_rn(o[mi][cn][0]);
            st[(c0 + 1) * 272 + q0]     = __float2half_rn(o[mi][cn][1]);
            st[c0 * 272 + q0 + 8]       = __float2half_rn(o[mi][cn][2]);
            st[(c0 + 1) * 272 + q0 + 8] = __float2half_rn(o[mi][cn][3]);
        }
    }
    __syncthreads();
    __half* gp = g_ph + ((size_t)quad * BB + b) * CC * NN + (size_t)qtile * 256;
    #pragma unroll
    for (int it = 0; it < 16; it++) {
        int i = tid + it * 256;
        int c = i >> 5, q8 = (i & 31) << 3;
        *(uint4*)(gp + (size_t)c * NN + q8) = *(uint4*)&st[c * 272 + q8];
    }
}

// ============================ combine quads (fp16 partials) ============================
__global__ __launch_bounds__(256)
void combine_kernel(float* __restrict__ out) {
    int idx = blockIdx.x * 256 + threadIdx.x;
    size_t e = (size_t)idx * 8;
    int n = (int)(e & (NN - 1));
    int b = (int)((e >> 19) & 1);             // CC*NN = 2^19

    float num[8] = {};
    float den[8] = {};
    #pragma unroll
    for (int p = 0; p < 4; p++) {
        uint4 u = *(const uint4*)(g_ph + (size_t)p * BB * CC * NN + e);
        float2 f0 = __half22float2(*(__half2*)&u.x);
        float2 f1 = __half22float2(*(__half2*)&u.y);
        float2 f2 = __half22float2(*(__half2*)&u.z);
        float2 f3 = __half22float2(*(__half2*)&u.w);
        num[0] += f0.x; num[1] += f0.y; num[2] += f1.x; num[3] += f1.y;
        num[4] += f2.x; num[5] += f2.y; num[6] += f3.x; num[7] += f3.y;
        const float* lp = g_lsum + ((size_t)p * BB + b) * NN + n;
        float4 la = *(const float4*)lp;
        float4 lb = *(const float4*)(lp + 4);
        den[0] += la.x; den[1] += la.y; den[2] += la.z; den[3] += la.w;
        den[4] += lb.x; den[5] += lb.y; den[6] += lb.z; den[7] += lb.w;
    }
    float4 r0, r1;
    r0.x = num[0] / den[0]; r0.y = num[1] / den[1];
    r0.z = num[2] / den[2]; r0.w = num[3] / den[3];
    r1.x = num[4] / den[4]; r1.y = num[5] / den[5];
    r1.z = num[6] / den[6]; r1.w = num[7] / den[7];
    *(float4*)(out + e) = r0;
    *(float4*)(out + e + 4) = r1;
}

// ============================ launch ============================
extern "C" void kernel_launch(void* const* d_in, const int* in_sizes, int n_in,
                              void* d_out, int out_size) {
    const float* x  = (const float*)d_in[0];
    const float* Wq = (const float*)d_in[1];
    const float* bq = (const float*)d_in[2];
    const float* Wk = (const float*)d_in[3];
    const float* bk = (const float*)d_in[4];
    const float* Wv = (const float*)d_in[5];
    const float* bv = (const float*)d_in[6];
    float* out = (float*)d_out;

    cudaFuncSetAttribute(qkv5, cudaFuncAttributeMaxDynamicSharedMemorySize, SMEM_QKV);
    dim3 gq(NN / 64, BB);
    qkv5<<<gq, 256, SMEM_QKV>>>(x, Wq, bq, Wk, bk, Wv, bv);

    cudaFuncSetAttribute(flash11, cudaFuncAttributeMaxDynamicSharedMemorySize, SMEM_FLASH11);
    dim3 gf(NN / 256, 4, BB);
    flash11<<<gf, 256, SMEM_FLASH11>>>();

    combine_kernel<<<(BB * CC * NN / 8) / 256, 256>>>(out);
}